// round 10
// baseline (speedup 1.0000x reference)
#include <cuda_runtime.h>
#include <cuda_bf16.h>
#include <cuda_fp16.h>
#include <cstdint>

// ============================================================================
// AWAttention on B200, baseline sm_100 mma.sync path.
//   Q = A@Wq^T + bq ; K = X@Wk^T + bk ; S = Q@K^T ; P = softmax(S) ; O = P@X
// Precision scheme (fp16 hi+lo split, 22 mantissa bits):
//   ABM=0 (Q/K/S): hh -> fp32-acc MMA ; hl+lh -> fp16-acc MMA; combined in
//                  epilogue. Missing ll term ~2^-22 (negligible).
//   ABM=2 (O):     P_fp16 @ Xhi_fp16, fp32 acc.
// Mainloop de-lockstep: each warp walks the 4 k-steps of a chunk starting at
// phase (wid%4), so LDSM phases of different warps overlap other warps' MMA
// phases (crossbar and tensor pipe run concurrently instead of additively).
// OUT modes: 0 = fp32 C ; 1 = split-fp16 (Chi,Clo) epilogue (Q/K).
// ============================================================================

#define SWZ(x) ((x) ^ (((x) >> 3) & 0x70))

__device__ __forceinline__ uint32_t smem_u32(const void* p) {
    uint32_t a;
    asm("{ .reg .u64 t; cvta.to.shared.u64 t, %1; cvt.u32.u64 %0, t; }" : "=r"(a) : "l"(p));
    return a;
}

#define CP_ASYNC16(sm, gm) \
    asm volatile("cp.async.cg.shared.global [%0], [%1], 16;" :: "r"(sm), "l"(gm))
#define CP_COMMIT() asm volatile("cp.async.commit_group;" ::: "memory")

__device__ __forceinline__ void ldmx4(uint32_t r[4], uint32_t addr) {
    asm volatile("ldmatrix.sync.aligned.m8n8.x4.shared.b16 {%0,%1,%2,%3}, [%4];"
                 : "=r"(r[0]), "=r"(r[1]), "=r"(r[2]), "=r"(r[3]) : "r"(addr));
}

// fp16 operands, fp32 accumulator
__device__ __forceinline__ void mma_f16(float c[4], const uint32_t a[4],
                                        uint32_t b0, uint32_t b1) {
    asm volatile(
        "mma.sync.aligned.m16n8k16.row.col.f32.f16.f16.f32 "
        "{%0,%1,%2,%3}, {%4,%5,%6,%7}, {%8,%9}, {%0,%1,%2,%3};"
        : "+f"(c[0]), "+f"(c[1]), "+f"(c[2]), "+f"(c[3])
        : "r"(a[0]), "r"(a[1]), "r"(a[2]), "r"(a[3]), "r"(b0), "r"(b1));
}

// fp16 operands, fp16 accumulator (2 x half2 regs)
__device__ __forceinline__ void mma_f16a(uint32_t c[2], const uint32_t a[4],
                                         uint32_t b0, uint32_t b1) {
    asm volatile(
        "mma.sync.aligned.m16n8k16.row.col.f16.f16.f16.f16 "
        "{%0,%1}, {%2,%3,%4,%5}, {%6,%7}, {%0,%1};"
        : "+r"(c[0]), "+r"(c[1])
        : "r"(a[0]), "r"(a[1]), "r"(a[2]), "r"(a[3]), "r"(b0), "r"(b1));
}

static constexpr int TILE_BYTES = 128 * 128;  // 128 rows x 128B (64 x 16-bit)

// ABM=0: 4 tiles/stage (Ah,Al,Bh,Bl), 3 stages -> 192KB
// ABM=2: 2 tiles/stage (Ah,Bh),       6 stages -> 192KB
template <int ABM> struct Cfg {
    static constexpr int NT  = (ABM == 0) ? 4 : 2;
    static constexpr int STG = (ABM == 0) ? 3 : 6;
    static constexpr int STAGE_B = NT * TILE_BYTES;
    static constexpr int SMEM = STG * STAGE_B;
};

template <int ABM>
__device__ __forceinline__ void load_chunk(
    uint32_t stage, const uint16_t* __restrict__ Ah, const uint16_t* __restrict__ Al,
    const uint16_t* __restrict__ Bh, const uint16_t* __restrict__ Bl,
    int m0, int n0, int kc, int K, int tid)
{
#pragma unroll
    for (int i = 0; i < 2; ++i) {
        int ch  = tid + i * 512;  // 0..1023
        int row = ch >> 3;
        int c16 = ch & 7;
        uint32_t soff = SWZ((uint32_t)(row * 128 + c16 * 16));
        size_t ga = ((size_t)(m0 + row) * K + (size_t)kc * 64) * 2 + (size_t)c16 * 16;
        size_t gb = ((size_t)(n0 + row) * K + (size_t)kc * 64) * 2 + (size_t)c16 * 16;
        if (ABM == 0) {
            CP_ASYNC16(stage + 0 * TILE_BYTES + soff, (const char*)Ah + ga);
            CP_ASYNC16(stage + 1 * TILE_BYTES + soff, (const char*)Al + ga);
            CP_ASYNC16(stage + 2 * TILE_BYTES + soff, (const char*)Bh + gb);
            CP_ASYNC16(stage + 3 * TILE_BYTES + soff, (const char*)Bl + gb);
        } else {
            CP_ASYNC16(stage + 0 * TILE_BYTES + soff, (const char*)Ah + ga);
            CP_ASYNC16(stage + 1 * TILE_BYTES + soff, (const char*)Bh + gb);
        }
    }
}

template <int ABM, int OUTM>
__global__ void __launch_bounds__(512, 1) gemm_kernel(
    const uint16_t* __restrict__ Ah, const uint16_t* __restrict__ Al,
    const uint16_t* __restrict__ Bh, const uint16_t* __restrict__ Bl,
    float* __restrict__ C, __half* __restrict__ Chi,
    __half* __restrict__ Clo, int M, int N, int K,
    const float* __restrict__ bias)
{
    constexpr int STG = Cfg<ABM>::STG;
    constexpr int STAGE_B = Cfg<ABM>::STAGE_B;

    extern __shared__ __align__(1024) unsigned char smem[];
    uint32_t sbase = smem_u32(smem);
    int tid = threadIdx.x, wid = tid >> 5, lane = tid & 31;
    int warp_m = wid & 3;   // 4 warps over M -> 32 rows each
    int warp_n = wid >> 2;  // 4 warps over N -> 32 cols each
    const int wphase = wid & 3;  // per-warp k-step phase rotation
    int m0 = blockIdx.y * 128, n0 = blockIdx.x * 128;

    float acc[2][4][4];
    uint32_t crs[2][4][2];  // fp16 cross-term accumulators (ABM=0 only)
#pragma unroll
    for (int i = 0; i < 2; ++i)
#pragma unroll
        for (int j = 0; j < 4; ++j) {
#pragma unroll
            for (int e = 0; e < 4; ++e) acc[i][j][e] = 0.0f;
            crs[i][j][0] = 0u; crs[i][j][1] = 0u;
        }

    const int nch = K >> 6;

#pragma unroll
    for (int s = 0; s < STG - 1; ++s) {
        if (s < nch)
            load_chunk<ABM>(sbase + s * STAGE_B, Ah, Al, Bh, Bl, m0, n0, s, K, tid);
        CP_COMMIT();
    }

    const int a_rowbase = warp_m * 32 + (lane & 15);
    const int a_colb    = (lane >> 4) * 16;
    const int b_rowbase = warp_n * 32 + (lane & 7) + ((lane >> 3) & 1) * 8;
    const int b_colb    = (lane >> 4) * 16;

    for (int c = 0; c < nch; ++c) {
        if constexpr (STG == 3)      asm volatile("cp.async.wait_group 1;" ::: "memory");
        else                         asm volatile("cp.async.wait_group 4;" ::: "memory");
        __syncthreads();

        int nextc = c + STG - 1;
        if (nextc < nch)
            load_chunk<ABM>(sbase + (uint32_t)(nextc % STG) * STAGE_B,
                            Ah, Al, Bh, Bl, m0, n0, nextc, K, tid);
        CP_COMMIT();

        uint32_t st = sbase + (uint32_t)(c % STG) * STAGE_B;

#pragma unroll
        for (int ks4 = 0; ks4 < 4; ++ks4) {
            const int ks = (ks4 + wphase) & 3;  // rotated k-step (all resident)
            if (ABM == 0) {
                uint32_t tAh = st, tAl = st + TILE_BYTES;
                uint32_t tBh = st + 2 * TILE_BYTES, tBl = st + 3 * TILE_BYTES;
                uint32_t ah[2][4], al[2][4];
#pragma unroll
                for (int i = 0; i < 2; ++i) {
                    uint32_t off = SWZ((uint32_t)((a_rowbase + i * 16) * 128 + ks * 32 + a_colb));
                    ldmx4(ah[i], tAh + off);
                    ldmx4(al[i], tAl + off);
                }
                uint32_t bh[4][2], bl[4][2];
#pragma unroll
                for (int jb = 0; jb < 2; ++jb) {
                    uint32_t off = SWZ((uint32_t)((b_rowbase + jb * 16) * 128 + ks * 32 + b_colb));
                    uint32_t r[4];
                    ldmx4(r, tBh + off);
                    bh[jb * 2 + 0][0] = r[0]; bh[jb * 2 + 0][1] = r[2];
                    bh[jb * 2 + 1][0] = r[1]; bh[jb * 2 + 1][1] = r[3];
                    ldmx4(r, tBl + off);
                    bl[jb * 2 + 0][0] = r[0]; bl[jb * 2 + 0][1] = r[2];
                    bl[jb * 2 + 1][0] = r[1]; bl[jb * 2 + 1][1] = r[3];
                }
                // Three independent passes (no back-to-back RAW on acc/crs)
#pragma unroll
                for (int i = 0; i < 2; ++i)
#pragma unroll
                    for (int j = 0; j < 4; ++j)
                        mma_f16 (acc[i][j], ah[i], bh[j][0], bh[j][1]);  // hh
#pragma unroll
                for (int i = 0; i < 2; ++i)
#pragma unroll
                    for (int j = 0; j < 4; ++j)
                        mma_f16a(crs[i][j], ah[i], bl[j][0], bl[j][1]);  // hl
#pragma unroll
                for (int i = 0; i < 2; ++i)
#pragma unroll
                    for (int j = 0; j < 4; ++j)
                        mma_f16a(crs[i][j], al[i], bh[j][0], bh[j][1]);  // lh
            } else {
                uint32_t tAh = st;
                uint32_t tBh = st + TILE_BYTES;
                uint32_t ah[2][4];
#pragma unroll
                for (int i = 0; i < 2; ++i) {
                    uint32_t off = SWZ((uint32_t)((a_rowbase + i * 16) * 128 + ks * 32 + a_colb));
                    ldmx4(ah[i], tAh + off);
                }
                uint32_t bh[4][2];
#pragma unroll
                for (int jb = 0; jb < 2; ++jb) {
                    uint32_t off = SWZ((uint32_t)((b_rowbase + jb * 16) * 128 + ks * 32 + b_colb));
                    uint32_t r[4];
                    ldmx4(r, tBh + off);
                    bh[jb * 2 + 0][0] = r[0]; bh[jb * 2 + 0][1] = r[2];
                    bh[jb * 2 + 1][0] = r[1]; bh[jb * 2 + 1][1] = r[3];
                }
#pragma unroll
                for (int i = 0; i < 2; ++i)
#pragma unroll
                    for (int j = 0; j < 4; ++j)
                        mma_f16(acc[i][j], ah[i], bh[j][0], bh[j][1]);
            }
        }
        __syncthreads();
    }

    // Epilogue: combine fp32 hh acc + fp16 cross acc, then store.
    int g = lane >> 2, t = lane & 3;
#pragma unroll
    for (int i = 0; i < 2; ++i) {
        int r0 = m0 + warp_m * 32 + i * 16 + g;
#pragma unroll
        for (int j = 0; j < 4; ++j) {
            int col = n0 + warp_n * 32 + j * 8 + t * 2;
            float v0 = acc[i][j][0], v1 = acc[i][j][1];
            float v2 = acc[i][j][2], v3 = acc[i][j][3];
            if (ABM == 0) {
                __half2 c01 = *(__half2*)&crs[i][j][0];
                __half2 c23 = *(__half2*)&crs[i][j][1];
                v0 += __low2float(c01);  v1 += __high2float(c01);
                v2 += __low2float(c23);  v3 += __high2float(c23);
            }
            if (bias) {
                float b0 = __ldg(bias + col), b1 = __ldg(bias + col + 1);
                v0 += b0; v1 += b1; v2 += b0; v3 += b1;
            }
            if constexpr (OUTM == 0) {
                *(float2*)(C + (size_t)r0 * N + col)       = make_float2(v0, v1);
                *(float2*)(C + (size_t)(r0 + 8) * N + col) = make_float2(v2, v3);
            } else {
                __half h0 = __float2half(v0), h1 = __float2half(v1);
                __half h2 = __float2half(v2), h3 = __float2half(v3);
                __half l0 = __float2half(v0 - __half2float(h0));
                __half l1 = __float2half(v1 - __half2float(h1));
                __half l2 = __float2half(v2 - __half2float(h2));
                __half l3 = __float2half(v3 - __half2float(h3));
                __half2 hh0; hh0.x = h0; hh0.y = h1;
                __half2 hh1; hh1.x = h2; hh1.y = h3;
                __half2 ll0; ll0.x = l0; ll0.y = l1;
                __half2 ll1; ll1.x = l2; ll1.y = l3;
                *(__half2*)(Chi + (size_t)r0 * N + col)       = hh0;
                *(__half2*)(Chi + (size_t)(r0 + 8) * N + col) = hh1;
                *(__half2*)(Clo + (size_t)r0 * N + col)       = ll0;
                *(__half2*)(Clo + (size_t)(r0 + 8) * N + col) = ll1;
            }
        }
    }
}

// ---------------------------------------------------------------------------
// Fused fp32 -> (fp16 hi, fp16 lo) split for A, Wq, Wk (one launch)
// ---------------------------------------------------------------------------
__device__ __forceinline__ void split_one(const float* __restrict__ in,
                                          __half* __restrict__ hi,
                                          __half* __restrict__ lo,
                                          long long n, long long gtid, long long stride)
{
    for (long long i = gtid; i < n; i += stride) {
        float x = in[i];
        __half h = __float2half(x);
        hi[i] = h;
        lo[i] = __float2half(x - __half2float(h));
    }
}

__global__ void fused_split_kernel(
    const float* __restrict__ A,  __half* Ahi,  __half* Alo,  long long nA,
    const float* __restrict__ W1, __half* W1hi, __half* W1lo,
    const float* __restrict__ W2, __half* W2hi, __half* W2lo, long long nW)
{
    long long gtid = (long long)blockIdx.x * blockDim.x + threadIdx.x;
    long long stride = (long long)gridDim.x * blockDim.x;
    split_one(A,  Ahi,  Alo,  nA, gtid, stride);
    split_one(W1, W1hi, W1lo, nW, gtid, stride);
    split_one(W2, W2hi, W2lo, nW, gtid, stride);
}

// ---------------------------------------------------------------------------
// X: one read -> (fp16 hi, fp16 lo) linear + fp16 transposed [C,R]
// ---------------------------------------------------------------------------
__global__ void xsplit_kernel(const float* __restrict__ X,
                              __half* __restrict__ hi,
                              __half* __restrict__ lo,
                              __half* __restrict__ xt, int R, int C)
{
    __shared__ float tbuf[32][33];
    int c0 = blockIdx.x * 32, r0 = blockIdx.y * 32;
    int tx = threadIdx.x, ty = threadIdx.y;  // 32 x 8
#pragma unroll
    for (int j = 0; j < 4; ++j) {
        int r = r0 + ty + 8 * j;
        float v = X[(long long)r * C + c0 + tx];
        tbuf[ty + 8 * j][tx] = v;
        __half h = __float2half(v);
        hi[(long long)r * C + c0 + tx] = h;
        lo[(long long)r * C + c0 + tx] = __float2half(v - __half2float(h));
    }
    __syncthreads();
#pragma unroll
    for (int j = 0; j < 4; ++j) {
        float v = tbuf[tx][ty + 8 * j];  // X[r0+tx][c0+ty+8j]
        xt[(long long)(c0 + ty + 8 * j) * R + r0 + tx] = __float2half(v);
    }
}

// ---------------------------------------------------------------------------
// Row softmax (N=8192) writing fp16 probabilities (single S read via smem buf)
// ---------------------------------------------------------------------------
__global__ void __launch_bounds__(256) softmax_kernel(
    const float* __restrict__ S, __half* __restrict__ P, int N)
{
    __shared__ float buf[8192];
    __shared__ float red[8];
    int row = blockIdx.x, tid = threadIdx.x;
    const float* s = S + (long long)row * N;

    float mx = -3.0e38f;
    for (int i = tid; i < N; i += 256) mx = fmaxf(mx, s[i]);
#pragma unroll
    for (int o = 16; o; o >>= 1) mx = fmaxf(mx, __shfl_xor_sync(0xFFFFFFFFu, mx, o));
    if ((tid & 31) == 0) red[tid >> 5] = mx;
    __syncthreads();
    mx = red[0];
#pragma unroll
    for (int w = 1; w < 8; ++w) mx = fmaxf(mx, red[w]);

    float sum = 0.0f;
    for (int i = tid; i < N; i += 256) {
        float e = __expf(s[i] - mx);
        buf[i] = e;
        sum += e;
    }
#pragma unroll
    for (int o = 16; o; o >>= 1) sum += __shfl_xor_sync(0xFFFFFFFFu, sum, o);
    __syncthreads();
    if ((tid & 31) == 0) red[tid >> 5] = sum;
    __syncthreads();
    sum = 0.0f;
#pragma unroll
    for (int w = 0; w < 8; ++w) sum += red[w];
    float inv = 1.0f / sum;

    for (int i = tid; i < N; i += 256)
        P[(long long)row * N + i] = __float2half(buf[i] * inv);
}

// ---------------------------------------------------------------------------
// Scratch
// ---------------------------------------------------------------------------
static constexpr size_t SZ_AX = (size_t)8192 * 1024;
static constexpr size_t SZ_W  = (size_t)512 * 1024;
static constexpr size_t SZ_QK = (size_t)8192 * 512;
static constexpr size_t SZ_S  = (size_t)8192 * 8192;

static constexpr size_t OFF_AHI  = 0;
static constexpr size_t OFF_ALO  = OFF_AHI  + SZ_AX * 2;
static constexpr size_t OFF_XHI  = OFF_ALO  + SZ_AX * 2;
static constexpr size_t OFF_XLO  = OFF_XHI  + SZ_AX * 2;
static constexpr size_t OFF_WQHI = OFF_XLO  + SZ_AX * 2;
static constexpr size_t OFF_WQLO = OFF_WQHI + SZ_W * 2;
static constexpr size_t OFF_WKHI = OFF_WQLO + SZ_W * 2;
static constexpr size_t OFF_WKLO = OFF_WKHI + SZ_W * 2;
static constexpr size_t OFF_QHI  = OFF_WKLO + SZ_W * 2;
static constexpr size_t OFF_QLO  = OFF_QHI  + SZ_QK * 2;
static constexpr size_t OFF_KHI  = OFF_QLO  + SZ_QK * 2;
static constexpr size_t OFF_KLO  = OFF_KHI  + SZ_QK * 2;
static constexpr size_t OFF_S    = OFF_KLO  + SZ_QK * 2;
static constexpr size_t OFF_PHI  = OFF_S    + SZ_S * 4;
static constexpr size_t OFF_XTHI = OFF_PHI  + SZ_S * 2;
static constexpr size_t SCRATCH_TOTAL = OFF_XTHI + SZ_AX * 2;

__device__ __align__(256) unsigned char g_scratch[SCRATCH_TOTAL];

// ---------------------------------------------------------------------------
// kernel_launch
// ---------------------------------------------------------------------------
extern "C" void kernel_launch(void* const* d_in, const int* in_sizes, int n_in,
                              void* d_out, int out_size)
{
    const float* A  = (const float*)d_in[0];
    const float* X  = (const float*)d_in[1];
    const float* Wq = (const float*)d_in[2];
    const float* bq = (const float*)d_in[3];
    const float* Wk = (const float*)d_in[4];
    const float* bk = (const float*)d_in[5];
    float* out = (float*)d_out;

    unsigned char* s = nullptr;
    cudaGetSymbolAddress((void**)&s, g_scratch);
    auto H  = [&](size_t off) { return (__half*)(s + off); };
    auto U16 = [&](size_t off) { return (const uint16_t*)(s + off); };
    auto F  = [&](size_t off) { return (float*)(s + off); };

    cudaFuncSetAttribute(gemm_kernel<0, 0>,
                         cudaFuncAttributeMaxDynamicSharedMemorySize, Cfg<0>::SMEM);
    cudaFuncSetAttribute(gemm_kernel<0, 1>,
                         cudaFuncAttributeMaxDynamicSharedMemorySize, Cfg<0>::SMEM);
    cudaFuncSetAttribute(gemm_kernel<2, 0>,
                         cudaFuncAttributeMaxDynamicSharedMemorySize, Cfg<2>::SMEM);

    // Splits: A/Wq/Wk (one launch) ; X -> hi/lo + fp16 transpose (one launch)
    fused_split_kernel<<<2048, 256>>>(
        A,  H(OFF_AHI),  H(OFF_ALO),  (long long)SZ_AX,
        Wq, H(OFF_WQHI), H(OFF_WQLO),
        Wk, H(OFF_WKHI), H(OFF_WKLO), (long long)SZ_W);
    xsplit_kernel<<<dim3(1024 / 32, 8192 / 32), dim3(32, 8)>>>(
        X, H(OFF_XHI), H(OFF_XLO), H(OFF_XTHI), 8192, 1024);

    // Q/K GEMMs with fused split-fp16 epilogue (M=8192, N=512, K=1024)
    dim3 gq(512 / 128, 8192 / 128);
    gemm_kernel<0, 1><<<gq, 512, Cfg<0>::SMEM>>>(
        U16(OFF_AHI), U16(OFF_ALO), U16(OFF_WQHI), U16(OFF_WQLO),
        nullptr, H(OFF_QHI), H(OFF_QLO), 8192, 512, 1024, bq);
    gemm_kernel<0, 1><<<gq, 512, Cfg<0>::SMEM>>>(
        U16(OFF_XHI), U16(OFF_XLO), U16(OFF_WKHI), U16(OFF_WKLO),
        nullptr, H(OFF_KHI), H(OFF_KLO), 8192, 512, 1024, bk);

    // S = Q @ K^T   (M=8192, N=8192, K=512)
    dim3 gs(8192 / 128, 8192 / 128);
    gemm_kernel<0, 0><<<gs, 512, Cfg<0>::SMEM>>>(
        U16(OFF_QHI), U16(OFF_QLO), U16(OFF_KHI), U16(OFF_KLO),
        F(OFF_S), nullptr, nullptr, 8192, 8192, 512, nullptr);

    // P = softmax(S) -> fp16
    softmax_kernel<<<8192, 256>>>(F(OFF_S), (__half*)(s + OFF_PHI), 8192);

    // O = P @ X   (M=8192, N=1024, K=8192), single fp16 MMA (fp32 acc)
    dim3 go(1024 / 128, 8192 / 128);
    gemm_kernel<2, 0><<<go, 512, Cfg<2>::SMEM>>>(
        U16(OFF_PHI), nullptr, U16(OFF_XTHI), nullptr,
        out, nullptr, nullptr, 8192, 1024, 8192, nullptr);
}

// round 11
// speedup vs baseline: 1.0045x; 1.0045x over previous
#include <cuda_runtime.h>
#include <cuda_bf16.h>
#include <cuda_fp16.h>
#include <cstdint>

// ============================================================================
// AWAttention on B200, baseline sm_100 mma.sync path.
//   Q = A@Wq^T + bq ; K = X@Wk^T + bk ; S = Q@K^T ; P = softmax(S) ; O = P@X
// Precision scheme (fp16 hi+lo split):
//   ABM=0 (Q/K/S): hh -> fp32-acc MMA ; hl+lh -> fp16-acc MMA.
//   ABM=2 (O):     P_fp16 @ Xhi_fp16, fp32 acc.
// R11: Q/K GEMMs run concurrently on two streams (fill wave tails);
//      S epilogue computes row max via monotone-encoded atomicMax so the
//      softmax kernel does a single gmem pass (no max pass).
// OUT modes: 0 = fp32 C ; 1 = split-fp16 epilogue (Q/K) ;
//            3 = fp32 C + row-max atomics (S).
// ============================================================================

#define SWZ(x) ((x) ^ (((x) >> 3) & 0x70))

__device__ __forceinline__ uint32_t smem_u32(const void* p) {
    uint32_t a;
    asm("{ .reg .u64 t; cvta.to.shared.u64 t, %1; cvt.u32.u64 %0, t; }" : "=r"(a) : "l"(p));
    return a;
}

// Monotone encode: enc(x) preserves float order in uint order.
__device__ __forceinline__ uint32_t enc_f32(float x) {
    uint32_t b = __float_as_uint(x);
    return (b & 0x80000000u) ? ~b : (b | 0x80000000u);
}
__device__ __forceinline__ float dec_f32(uint32_t u) {
    uint32_t b = (u & 0x80000000u) ? (u ^ 0x80000000u) : ~u;
    return __uint_as_float(b);
}
static constexpr uint32_t ENC_NEG_INF = 0x007FFFFFu;  // enc(-inf)

#define CP_ASYNC16(sm, gm) \
    asm volatile("cp.async.cg.shared.global [%0], [%1], 16;" :: "r"(sm), "l"(gm))
#define CP_COMMIT() asm volatile("cp.async.commit_group;" ::: "memory")

__device__ __forceinline__ void ldmx4(uint32_t r[4], uint32_t addr) {
    asm volatile("ldmatrix.sync.aligned.m8n8.x4.shared.b16 {%0,%1,%2,%3}, [%4];"
                 : "=r"(r[0]), "=r"(r[1]), "=r"(r[2]), "=r"(r[3]) : "r"(addr));
}

__device__ __forceinline__ void mma_f16(float c[4], const uint32_t a[4],
                                        uint32_t b0, uint32_t b1) {
    asm volatile(
        "mma.sync.aligned.m16n8k16.row.col.f32.f16.f16.f32 "
        "{%0,%1,%2,%3}, {%4,%5,%6,%7}, {%8,%9}, {%0,%1,%2,%3};"
        : "+f"(c[0]), "+f"(c[1]), "+f"(c[2]), "+f"(c[3])
        : "r"(a[0]), "r"(a[1]), "r"(a[2]), "r"(a[3]), "r"(b0), "r"(b1));
}

__device__ __forceinline__ void mma_f16a(uint32_t c[2], const uint32_t a[4],
                                         uint32_t b0, uint32_t b1) {
    asm volatile(
        "mma.sync.aligned.m16n8k16.row.col.f16.f16.f16.f16 "
        "{%0,%1}, {%2,%3,%4,%5}, {%6,%7}, {%0,%1};"
        : "+r"(c[0]), "+r"(c[1])
        : "r"(a[0]), "r"(a[1]), "r"(a[2]), "r"(a[3]), "r"(b0), "r"(b1));
}

static constexpr int TILE_BYTES = 128 * 128;

template <int ABM> struct Cfg {
    static constexpr int NT  = (ABM == 0) ? 4 : 2;
    static constexpr int STG = (ABM == 0) ? 3 : 6;
    static constexpr int STAGE_B = NT * TILE_BYTES;
    static constexpr int SMEM = STG * STAGE_B;
};

template <int ABM>
__device__ __forceinline__ void load_chunk(
    uint32_t stage, const uint16_t* __restrict__ Ah, const uint16_t* __restrict__ Al,
    const uint16_t* __restrict__ Bh, const uint16_t* __restrict__ Bl,
    int m0, int n0, int kc, int K, int tid)
{
#pragma unroll
    for (int i = 0; i < 2; ++i) {
        int ch  = tid + i * 512;
        int row = ch >> 3;
        int c16 = ch & 7;
        uint32_t soff = SWZ((uint32_t)(row * 128 + c16 * 16));
        size_t ga = ((size_t)(m0 + row) * K + (size_t)kc * 64) * 2 + (size_t)c16 * 16;
        size_t gb = ((size_t)(n0 + row) * K + (size_t)kc * 64) * 2 + (size_t)c16 * 16;
        if (ABM == 0) {
            CP_ASYNC16(stage + 0 * TILE_BYTES + soff, (const char*)Ah + ga);
            CP_ASYNC16(stage + 1 * TILE_BYTES + soff, (const char*)Al + ga);
            CP_ASYNC16(stage + 2 * TILE_BYTES + soff, (const char*)Bh + gb);
            CP_ASYNC16(stage + 3 * TILE_BYTES + soff, (const char*)Bl + gb);
        } else {
            CP_ASYNC16(stage + 0 * TILE_BYTES + soff, (const char*)Ah + ga);
            CP_ASYNC16(stage + 1 * TILE_BYTES + soff, (const char*)Bh + gb);
        }
    }
}

template <int ABM, int OUTM>
__global__ void __launch_bounds__(512, 1) gemm_kernel(
    const uint16_t* __restrict__ Ah, const uint16_t* __restrict__ Al,
    const uint16_t* __restrict__ Bh, const uint16_t* __restrict__ Bl,
    float* __restrict__ C, __half* __restrict__ Chi,
    __half* __restrict__ Clo, uint32_t* __restrict__ RM,
    int M, int N, int K, const float* __restrict__ bias)
{
    constexpr int STG = Cfg<ABM>::STG;
    constexpr int STAGE_B = Cfg<ABM>::STAGE_B;

    extern __shared__ __align__(1024) unsigned char smem[];
    uint32_t sbase = smem_u32(smem);
    int tid = threadIdx.x, wid = tid >> 5, lane = tid & 31;
    int warp_m = wid & 3;
    int warp_n = wid >> 2;
    int m0 = blockIdx.y * 128, n0 = blockIdx.x * 128;

    float acc[2][4][4];
    uint32_t crs[2][4][2];
#pragma unroll
    for (int i = 0; i < 2; ++i)
#pragma unroll
        for (int j = 0; j < 4; ++j) {
#pragma unroll
            for (int e = 0; e < 4; ++e) acc[i][j][e] = 0.0f;
            crs[i][j][0] = 0u; crs[i][j][1] = 0u;
        }

    const int nch = K >> 6;

#pragma unroll
    for (int s = 0; s < STG - 1; ++s) {
        if (s < nch)
            load_chunk<ABM>(sbase + s * STAGE_B, Ah, Al, Bh, Bl, m0, n0, s, K, tid);
        CP_COMMIT();
    }

    const int a_rowbase = warp_m * 32 + (lane & 15);
    const int a_colb    = (lane >> 4) * 16;
    const int b_rowbase = warp_n * 32 + (lane & 7) + ((lane >> 3) & 1) * 8;
    const int b_colb    = (lane >> 4) * 16;

    for (int c = 0; c < nch; ++c) {
        if constexpr (STG == 3)      asm volatile("cp.async.wait_group 1;" ::: "memory");
        else                         asm volatile("cp.async.wait_group 4;" ::: "memory");
        __syncthreads();

        int nextc = c + STG - 1;
        if (nextc < nch)
            load_chunk<ABM>(sbase + (uint32_t)(nextc % STG) * STAGE_B,
                            Ah, Al, Bh, Bl, m0, n0, nextc, K, tid);
        CP_COMMIT();

        uint32_t st = sbase + (uint32_t)(c % STG) * STAGE_B;

#pragma unroll
        for (int ks = 0; ks < 4; ++ks) {
            if (ABM == 0) {
                uint32_t tAh = st, tAl = st + TILE_BYTES;
                uint32_t tBh = st + 2 * TILE_BYTES, tBl = st + 3 * TILE_BYTES;
                uint32_t ah[2][4], al[2][4];
#pragma unroll
                for (int i = 0; i < 2; ++i) {
                    uint32_t off = SWZ((uint32_t)((a_rowbase + i * 16) * 128 + ks * 32 + a_colb));
                    ldmx4(ah[i], tAh + off);
                    ldmx4(al[i], tAl + off);
                }
                uint32_t bh[4][2], bl[4][2];
#pragma unroll
                for (int jb = 0; jb < 2; ++jb) {
                    uint32_t off = SWZ((uint32_t)((b_rowbase + jb * 16) * 128 + ks * 32 + b_colb));
                    uint32_t r[4];
                    ldmx4(r, tBh + off);
                    bh[jb * 2 + 0][0] = r[0]; bh[jb * 2 + 0][1] = r[2];
                    bh[jb * 2 + 1][0] = r[1]; bh[jb * 2 + 1][1] = r[3];
                    ldmx4(r, tBl + off);
                    bl[jb * 2 + 0][0] = r[0]; bl[jb * 2 + 0][1] = r[2];
                    bl[jb * 2 + 1][0] = r[1]; bl[jb * 2 + 1][1] = r[3];
                }
#pragma unroll
                for (int i = 0; i < 2; ++i)
#pragma unroll
                    for (int j = 0; j < 4; ++j)
                        mma_f16 (acc[i][j], ah[i], bh[j][0], bh[j][1]);  // hh
#pragma unroll
                for (int i = 0; i < 2; ++i)
#pragma unroll
                    for (int j = 0; j < 4; ++j)
                        mma_f16a(crs[i][j], ah[i], bl[j][0], bl[j][1]);  // hl
#pragma unroll
                for (int i = 0; i < 2; ++i)
#pragma unroll
                    for (int j = 0; j < 4; ++j)
                        mma_f16a(crs[i][j], al[i], bh[j][0], bh[j][1]);  // lh
            } else {
                uint32_t tAh = st;
                uint32_t tBh = st + TILE_BYTES;
                uint32_t ah[2][4];
#pragma unroll
                for (int i = 0; i < 2; ++i) {
                    uint32_t off = SWZ((uint32_t)((a_rowbase + i * 16) * 128 + ks * 32 + a_colb));
                    ldmx4(ah[i], tAh + off);
                }
                uint32_t bh[4][2];
#pragma unroll
                for (int jb = 0; jb < 2; ++jb) {
                    uint32_t off = SWZ((uint32_t)((b_rowbase + jb * 16) * 128 + ks * 32 + b_colb));
                    uint32_t r[4];
                    ldmx4(r, tBh + off);
                    bh[jb * 2 + 0][0] = r[0]; bh[jb * 2 + 0][1] = r[2];
                    bh[jb * 2 + 1][0] = r[1]; bh[jb * 2 + 1][1] = r[3];
                }
#pragma unroll
                for (int i = 0; i < 2; ++i)
#pragma unroll
                    for (int j = 0; j < 4; ++j)
                        mma_f16(acc[i][j], ah[i], bh[j][0], bh[j][1]);
            }
        }
        __syncthreads();
    }

    // Epilogue
    int g = lane >> 2, t = lane & 3;
#pragma unroll
    for (int i = 0; i < 2; ++i) {
        int r0 = m0 + warp_m * 32 + i * 16 + g;
        float rmax_lo = -3.0e38f, rmax_hi = -3.0e38f;  // OUTM==3 row maxima
#pragma unroll
        for (int j = 0; j < 4; ++j) {
            int col = n0 + warp_n * 32 + j * 8 + t * 2;
            float v0 = acc[i][j][0], v1 = acc[i][j][1];
            float v2 = acc[i][j][2], v3 = acc[i][j][3];
            if (ABM == 0) {
                __half2 c01 = *(__half2*)&crs[i][j][0];
                __half2 c23 = *(__half2*)&crs[i][j][1];
                v0 += __low2float(c01);  v1 += __high2float(c01);
                v2 += __low2float(c23);  v3 += __high2float(c23);
            }
            if (bias) {
                float b0 = __ldg(bias + col), b1 = __ldg(bias + col + 1);
                v0 += b0; v1 += b1; v2 += b0; v3 += b1;
            }
            if constexpr (OUTM == 0 || OUTM == 3) {
                *(float2*)(C + (size_t)r0 * N + col)       = make_float2(v0, v1);
                *(float2*)(C + (size_t)(r0 + 8) * N + col) = make_float2(v2, v3);
                if constexpr (OUTM == 3) {
                    rmax_lo = fmaxf(rmax_lo, fmaxf(v0, v1));
                    rmax_hi = fmaxf(rmax_hi, fmaxf(v2, v3));
                }
            } else {
                __half h0 = __float2half(v0), h1 = __float2half(v1);
                __half h2 = __float2half(v2), h3 = __float2half(v3);
                __half l0 = __float2half(v0 - __half2float(h0));
                __half l1 = __float2half(v1 - __half2float(h1));
                __half l2 = __float2half(v2 - __half2float(h2));
                __half l3 = __float2half(v3 - __half2float(h3));
                __half2 hh0; hh0.x = h0; hh0.y = h1;
                __half2 hh1; hh1.x = h2; hh1.y = h3;
                __half2 ll0; ll0.x = l0; ll0.y = l1;
                __half2 ll1; ll1.x = l2; ll1.y = l3;
                *(__half2*)(Chi + (size_t)r0 * N + col)       = hh0;
                *(__half2*)(Chi + (size_t)(r0 + 8) * N + col) = hh1;
                *(__half2*)(Clo + (size_t)r0 * N + col)       = ll0;
                *(__half2*)(Clo + (size_t)(r0 + 8) * N + col) = ll1;
            }
        }
        if constexpr (OUTM == 3) {
            // Reduce over the 4 lanes sharing each row (t = 0..3), then atomicMax.
            rmax_lo = fmaxf(rmax_lo, __shfl_xor_sync(0xFFFFFFFFu, rmax_lo, 1));
            rmax_lo = fmaxf(rmax_lo, __shfl_xor_sync(0xFFFFFFFFu, rmax_lo, 2));
            rmax_hi = fmaxf(rmax_hi, __shfl_xor_sync(0xFFFFFFFFu, rmax_hi, 1));
            rmax_hi = fmaxf(rmax_hi, __shfl_xor_sync(0xFFFFFFFFu, rmax_hi, 2));
            if (t == 0) {
                atomicMax(RM + r0,     enc_f32(rmax_lo));
                atomicMax(RM + r0 + 8, enc_f32(rmax_hi));
            }
        }
    }
}

// ---------------------------------------------------------------------------
// Fused fp32 -> (fp16 hi, fp16 lo) split for A, Wq, Wk + row-max init
// ---------------------------------------------------------------------------
__device__ __forceinline__ void split_one(const float* __restrict__ in,
                                          __half* __restrict__ hi,
                                          __half* __restrict__ lo,
                                          long long n, long long gtid, long long stride)
{
    for (long long i = gtid; i < n; i += stride) {
        float x = in[i];
        __half h = __float2half(x);
        hi[i] = h;
        lo[i] = __float2half(x - __half2float(h));
    }
}

__global__ void fused_split_kernel(
    const float* __restrict__ A,  __half* Ahi,  __half* Alo,  long long nA,
    const float* __restrict__ W1, __half* W1hi, __half* W1lo,
    const float* __restrict__ W2, __half* W2hi, __half* W2lo, long long nW,
    uint32_t* __restrict__ RM)
{
    long long gtid = (long long)blockIdx.x * blockDim.x + threadIdx.x;
    long long stride = (long long)gridDim.x * blockDim.x;
    if (gtid < 8192) RM[gtid] = ENC_NEG_INF;  // init row-max accumulators
    split_one(A,  Ahi,  Alo,  nA, gtid, stride);
    split_one(W1, W1hi, W1lo, nW, gtid, stride);
    split_one(W2, W2hi, W2lo, nW, gtid, stride);
}

// ---------------------------------------------------------------------------
// X: one read -> (fp16 hi, fp16 lo) linear + fp16 transposed [C,R]
// ---------------------------------------------------------------------------
__global__ void xsplit_kernel(const float* __restrict__ X,
                              __half* __restrict__ hi,
                              __half* __restrict__ lo,
                              __half* __restrict__ xt, int R, int C)
{
    __shared__ float tbuf[32][33];
    int c0 = blockIdx.x * 32, r0 = blockIdx.y * 32;
    int tx = threadIdx.x, ty = threadIdx.y;
#pragma unroll
    for (int j = 0; j < 4; ++j) {
        int r = r0 + ty + 8 * j;
        float v = X[(long long)r * C + c0 + tx];
        tbuf[ty + 8 * j][tx] = v;
        __half h = __float2half(v);
        hi[(long long)r * C + c0 + tx] = h;
        lo[(long long)r * C + c0 + tx] = __float2half(v - __half2float(h));
    }
    __syncthreads();
#pragma unroll
    for (int j = 0; j < 4; ++j) {
        float v = tbuf[tx][ty + 8 * j];
        xt[(long long)(c0 + ty + 8 * j) * R + r0 + tx] = __float2half(v);
    }
}

// ---------------------------------------------------------------------------
// Row softmax with precomputed row max (single gmem pass over S)
// ---------------------------------------------------------------------------
__global__ void __launch_bounds__(256) softmax_kernel(
    const float* __restrict__ S, const uint32_t* __restrict__ RM,
    __half* __restrict__ P, int N)
{
    __shared__ float buf[8192];
    __shared__ float red[8];
    int row = blockIdx.x, tid = threadIdx.x;
    const float* s = S + (long long)row * N;
    float mx = dec_f32(__ldg(RM + row));

    float sum = 0.0f;
    for (int i = tid; i < N; i += 256) {
        float e = __expf(s[i] - mx);
        buf[i] = e;
        sum += e;
    }
#pragma unroll
    for (int o = 16; o; o >>= 1) sum += __shfl_xor_sync(0xFFFFFFFFu, sum, o);
    if ((tid & 31) == 0) red[tid >> 5] = sum;
    __syncthreads();
    sum = 0.0f;
#pragma unroll
    for (int w = 0; w < 8; ++w) sum += red[w];
    float inv = 1.0f / sum;

    for (int i = tid; i < N; i += 256)
        P[(long long)row * N + i] = __float2half(buf[i] * inv);
}

// ---------------------------------------------------------------------------
// Scratch
// ---------------------------------------------------------------------------
static constexpr size_t SZ_AX = (size_t)8192 * 1024;
static constexpr size_t SZ_W  = (size_t)512 * 1024;
static constexpr size_t SZ_QK = (size_t)8192 * 512;
static constexpr size_t SZ_S  = (size_t)8192 * 8192;

static constexpr size_t OFF_AHI  = 0;
static constexpr size_t OFF_ALO  = OFF_AHI  + SZ_AX * 2;
static constexpr size_t OFF_XHI  = OFF_ALO  + SZ_AX * 2;
static constexpr size_t OFF_XLO  = OFF_XHI  + SZ_AX * 2;
static constexpr size_t OFF_WQHI = OFF_XLO  + SZ_AX * 2;
static constexpr size_t OFF_WQLO = OFF_WQHI + SZ_W * 2;
static constexpr size_t OFF_WKHI = OFF_WQLO + SZ_W * 2;
static constexpr size_t OFF_WKLO = OFF_WKHI + SZ_W * 2;
static constexpr size_t OFF_QHI  = OFF_WKLO + SZ_W * 2;
static constexpr size_t OFF_QLO  = OFF_QHI  + SZ_QK * 2;
static constexpr size_t OFF_KHI  = OFF_QLO  + SZ_QK * 2;
static constexpr size_t OFF_KLO  = OFF_KHI  + SZ_QK * 2;
static constexpr size_t OFF_S    = OFF_KLO  + SZ_QK * 2;
static constexpr size_t OFF_PHI  = OFF_S    + SZ_S * 4;
static constexpr size_t OFF_XTHI = OFF_PHI  + SZ_S * 2;
static constexpr size_t OFF_RM   = OFF_XTHI + SZ_AX * 2;
static constexpr size_t SCRATCH_TOTAL = OFF_RM + 8192 * 4;

__device__ __align__(256) unsigned char g_scratch[SCRATCH_TOTAL];

// ---------------------------------------------------------------------------
// kernel_launch
// ---------------------------------------------------------------------------
extern "C" void kernel_launch(void* const* d_in, const int* in_sizes, int n_in,
                              void* d_out, int out_size)
{
    const float* A  = (const float*)d_in[0];
    const float* X  = (const float*)d_in[1];
    const float* Wq = (const float*)d_in[2];
    const float* bq = (const float*)d_in[3];
    const float* Wk = (const float*)d_in[4];
    const float* bk = (const float*)d_in[5];
    float* out = (float*)d_out;

    unsigned char* s = nullptr;
    cudaGetSymbolAddress((void**)&s, g_scratch);
    auto H   = [&](size_t off) { return (__half*)(s + off); };
    auto U16 = [&](size_t off) { return (const uint16_t*)(s + off); };
    auto F   = [&](size_t off) { return (float*)(s + off); };
    uint32_t* RM = (uint32_t*)(s + OFF_RM);

    // One-time stream/event setup (first call is not graph-captured).
    static cudaStream_t s1 = nullptr;
    static cudaEvent_t evRoot = nullptr, evSplit = nullptr, evQ = nullptr;
    if (!s1) {
        cudaStreamCreateWithFlags(&s1, cudaStreamNonBlocking);
        cudaEventCreateWithFlags(&evRoot,  cudaEventDisableTiming);
        cudaEventCreateWithFlags(&evSplit, cudaEventDisableTiming);
        cudaEventCreateWithFlags(&evQ,     cudaEventDisableTiming);
    }

    cudaFuncSetAttribute(gemm_kernel<0, 3>,
                         cudaFuncAttributeMaxDynamicSharedMemorySize, Cfg<0>::SMEM);
    cudaFuncSetAttribute(gemm_kernel<0, 1>,
                         cudaFuncAttributeMaxDynamicSharedMemorySize, Cfg<0>::SMEM);
    cudaFuncSetAttribute(gemm_kernel<2, 0>,
                         cudaFuncAttributeMaxDynamicSharedMemorySize, Cfg<2>::SMEM);

    // Fork side stream from main stream.
    cudaEventRecord(evRoot, 0);
    cudaStreamWaitEvent(s1, evRoot, 0);

    // s1: split A/Wq/Wk (+RM init), then Q GEMM.
    fused_split_kernel<<<2048, 256, 0, s1>>>(
        A,  H(OFF_AHI),  H(OFF_ALO),  (long long)SZ_AX,
        Wq, H(OFF_WQHI), H(OFF_WQLO),
        Wk, H(OFF_WKHI), H(OFF_WKLO), (long long)SZ_W, RM);
    cudaEventRecord(evSplit, s1);

    dim3 gq(512 / 128, 8192 / 128);
    gemm_kernel<0, 1><<<gq, 512, Cfg<0>::SMEM, s1>>>(
        U16(OFF_AHI), U16(OFF_ALO), U16(OFF_WQHI), U16(OFF_WQLO),
        nullptr, H(OFF_QHI), H(OFF_QLO), nullptr, 8192, 512, 1024, bq);
    cudaEventRecord(evQ, s1);

    // main stream: X split (concurrent with fused_split), then K GEMM
    // (needs Wk halves from s1 -> wait evSplit; runs concurrent with Q GEMM).
    xsplit_kernel<<<dim3(1024 / 32, 8192 / 32), dim3(32, 8)>>>(
        X, H(OFF_XHI), H(OFF_XLO), H(OFF_XTHI), 8192, 1024);
    cudaStreamWaitEvent(0, evSplit, 0);
    gemm_kernel<0, 1><<<gq, 512, Cfg<0>::SMEM>>>(
        U16(OFF_XHI), U16(OFF_XLO), U16(OFF_WKHI), U16(OFF_WKLO),
        nullptr, H(OFF_KHI), H(OFF_KLO), nullptr, 8192, 512, 1024, bk);

    // Join: S needs Q (s1) and K (main).
    cudaStreamWaitEvent(0, evQ, 0);

    // S = Q @ K^T with row-max epilogue (M=N=8192, K=512)
    dim3 gs(8192 / 128, 8192 / 128);
    gemm_kernel<0, 3><<<gs, 512, Cfg<0>::SMEM>>>(
        U16(OFF_QHI), U16(OFF_QLO), U16(OFF_KHI), U16(OFF_KLO),
        F(OFF_S), nullptr, nullptr, RM, 8192, 8192, 512, nullptr);

    // P = softmax(S) -> fp16 (single pass; max precomputed)
    softmax_kernel<<<8192, 256>>>(F(OFF_S), RM, (__half*)(s + OFF_PHI), 8192);

    // O = P @ X (M=8192, N=1024, K=8192)
    dim3 go(1024 / 128, 8192 / 128);
    gemm_kernel<2, 0><<<go, 512, Cfg<2>::SMEM>>>(
        U16(OFF_PHI), nullptr, U16(OFF_XTHI), nullptr,
        out, nullptr, nullptr, nullptr, 8192, 1024, 8192, nullptr);
}

// round 12
// speedup vs baseline: 1.0062x; 1.0017x over previous
#include <cuda_runtime.h>
#include <cuda_bf16.h>
#include <cuda_fp16.h>
#include <cstdint>

// ============================================================================
// AWAttention on B200, baseline sm_100 mma.sync path.
//   Q = A@Wq^T + bq ; K = X@Wk^T + bk ; S = Q@K^T ; P = softmax(S) ; O = P@X
// Precision scheme (fp16 hi+lo split):
//   ABM=0 (Q/K/S): hh -> fp32-acc MMA ; hl+lh -> fp16-acc MMA.
//   ABM=2 (O):     P_fp16 @ Xhi_fp16, fp32 acc.
// R11: Q/K GEMMs run concurrently on two streams (fill wave tails);
//      S epilogue computes row max via monotone-encoded atomicMax so the
//      softmax kernel does a single gmem pass (no max pass).
// OUT modes: 0 = fp32 C ; 1 = split-fp16 epilogue (Q/K) ;
//            3 = fp32 C + row-max atomics (S).
// ============================================================================

#define SWZ(x) ((x) ^ (((x) >> 3) & 0x70))

__device__ __forceinline__ uint32_t smem_u32(const void* p) {
    uint32_t a;
    asm("{ .reg .u64 t; cvta.to.shared.u64 t, %1; cvt.u32.u64 %0, t; }" : "=r"(a) : "l"(p));
    return a;
}

// Monotone encode: enc(x) preserves float order in uint order.
__device__ __forceinline__ uint32_t enc_f32(float x) {
    uint32_t b = __float_as_uint(x);
    return (b & 0x80000000u) ? ~b : (b | 0x80000000u);
}
__device__ __forceinline__ float dec_f32(uint32_t u) {
    uint32_t b = (u & 0x80000000u) ? (u ^ 0x80000000u) : ~u;
    return __uint_as_float(b);
}
static constexpr uint32_t ENC_NEG_INF = 0x007FFFFFu;  // enc(-inf)

#define CP_ASYNC16(sm, gm) \
    asm volatile("cp.async.cg.shared.global [%0], [%1], 16;" :: "r"(sm), "l"(gm))
#define CP_COMMIT() asm volatile("cp.async.commit_group;" ::: "memory")

__device__ __forceinline__ void ldmx4(uint32_t r[4], uint32_t addr) {
    asm volatile("ldmatrix.sync.aligned.m8n8.x4.shared.b16 {%0,%1,%2,%3}, [%4];"
                 : "=r"(r[0]), "=r"(r[1]), "=r"(r[2]), "=r"(r[3]) : "r"(addr));
}

__device__ __forceinline__ void mma_f16(float c[4], const uint32_t a[4],
                                        uint32_t b0, uint32_t b1) {
    asm volatile(
        "mma.sync.aligned.m16n8k16.row.col.f32.f16.f16.f32 "
        "{%0,%1,%2,%3}, {%4,%5,%6,%7}, {%8,%9}, {%0,%1,%2,%3};"
        : "+f"(c[0]), "+f"(c[1]), "+f"(c[2]), "+f"(c[3])
        : "r"(a[0]), "r"(a[1]), "r"(a[2]), "r"(a[3]), "r"(b0), "r"(b1));
}

__device__ __forceinline__ void mma_f16a(uint32_t c[2], const uint32_t a[4],
                                         uint32_t b0, uint32_t b1) {
    asm volatile(
        "mma.sync.aligned.m16n8k16.row.col.f16.f16.f16.f16 "
        "{%0,%1}, {%2,%3,%4,%5}, {%6,%7}, {%0,%1};"
        : "+r"(c[0]), "+r"(c[1])
        : "r"(a[0]), "r"(a[1]), "r"(a[2]), "r"(a[3]), "r"(b0), "r"(b1));
}

static constexpr int TILE_BYTES = 128 * 128;

template <int ABM> struct Cfg {
    static constexpr int NT  = (ABM == 0) ? 4 : 2;
    static constexpr int STG = (ABM == 0) ? 3 : 6;
    static constexpr int STAGE_B = NT * TILE_BYTES;
    static constexpr int SMEM = STG * STAGE_B;
};

template <int ABM>
__device__ __forceinline__ void load_chunk(
    uint32_t stage, const uint16_t* __restrict__ Ah, const uint16_t* __restrict__ Al,
    const uint16_t* __restrict__ Bh, const uint16_t* __restrict__ Bl,
    int m0, int n0, int kc, int K, int tid)
{
#pragma unroll
    for (int i = 0; i < 2; ++i) {
        int ch  = tid + i * 512;
        int row = ch >> 3;
        int c16 = ch & 7;
        uint32_t soff = SWZ((uint32_t)(row * 128 + c16 * 16));
        size_t ga = ((size_t)(m0 + row) * K + (size_t)kc * 64) * 2 + (size_t)c16 * 16;
        size_t gb = ((size_t)(n0 + row) * K + (size_t)kc * 64) * 2 + (size_t)c16 * 16;
        if (ABM == 0) {
            CP_ASYNC16(stage + 0 * TILE_BYTES + soff, (const char*)Ah + ga);
            CP_ASYNC16(stage + 1 * TILE_BYTES + soff, (const char*)Al + ga);
            CP_ASYNC16(stage + 2 * TILE_BYTES + soff, (const char*)Bh + gb);
            CP_ASYNC16(stage + 3 * TILE_BYTES + soff, (const char*)Bl + gb);
        } else {
            CP_ASYNC16(stage + 0 * TILE_BYTES + soff, (const char*)Ah + ga);
            CP_ASYNC16(stage + 1 * TILE_BYTES + soff, (const char*)Bh + gb);
        }
    }
}

template <int ABM, int OUTM>
__global__ void __launch_bounds__(512, 1) gemm_kernel(
    const uint16_t* __restrict__ Ah, const uint16_t* __restrict__ Al,
    const uint16_t* __restrict__ Bh, const uint16_t* __restrict__ Bl,
    float* __restrict__ C, __half* __restrict__ Chi,
    __half* __restrict__ Clo, uint32_t* __restrict__ RM,
    int M, int N, int K, const float* __restrict__ bias)
{
    constexpr int STG = Cfg<ABM>::STG;
    constexpr int STAGE_B = Cfg<ABM>::STAGE_B;

    extern __shared__ __align__(1024) unsigned char smem[];
    uint32_t sbase = smem_u32(smem);
    int tid = threadIdx.x, wid = tid >> 5, lane = tid & 31;
    int warp_m = wid & 3;
    int warp_n = wid >> 2;
    int m0 = blockIdx.y * 128, n0 = blockIdx.x * 128;

    float acc[2][4][4];
    uint32_t crs[2][4][2];
#pragma unroll
    for (int i = 0; i < 2; ++i)
#pragma unroll
        for (int j = 0; j < 4; ++j) {
#pragma unroll
            for (int e = 0; e < 4; ++e) acc[i][j][e] = 0.0f;
            crs[i][j][0] = 0u; crs[i][j][1] = 0u;
        }

    const int nch = K >> 6;

#pragma unroll
    for (int s = 0; s < STG - 1; ++s) {
        if (s < nch)
            load_chunk<ABM>(sbase + s * STAGE_B, Ah, Al, Bh, Bl, m0, n0, s, K, tid);
        CP_COMMIT();
    }

    const int a_rowbase = warp_m * 32 + (lane & 15);
    const int a_colb    = (lane >> 4) * 16;
    const int b_rowbase = warp_n * 32 + (lane & 7) + ((lane >> 3) & 1) * 8;
    const int b_colb    = (lane >> 4) * 16;

    for (int c = 0; c < nch; ++c) {
        if constexpr (STG == 3)      asm volatile("cp.async.wait_group 1;" ::: "memory");
        else                         asm volatile("cp.async.wait_group 4;" ::: "memory");
        __syncthreads();

        int nextc = c + STG - 1;
        if (nextc < nch)
            load_chunk<ABM>(sbase + (uint32_t)(nextc % STG) * STAGE_B,
                            Ah, Al, Bh, Bl, m0, n0, nextc, K, tid);
        CP_COMMIT();

        uint32_t st = sbase + (uint32_t)(c % STG) * STAGE_B;

#pragma unroll
        for (int ks = 0; ks < 4; ++ks) {
            if (ABM == 0) {
                uint32_t tAh = st, tAl = st + TILE_BYTES;
                uint32_t tBh = st + 2 * TILE_BYTES, tBl = st + 3 * TILE_BYTES;
                uint32_t ah[2][4], al[2][4];
#pragma unroll
                for (int i = 0; i < 2; ++i) {
                    uint32_t off = SWZ((uint32_t)((a_rowbase + i * 16) * 128 + ks * 32 + a_colb));
                    ldmx4(ah[i], tAh + off);
                    ldmx4(al[i], tAl + off);
                }
                uint32_t bh[4][2], bl[4][2];
#pragma unroll
                for (int jb = 0; jb < 2; ++jb) {
                    uint32_t off = SWZ((uint32_t)((b_rowbase + jb * 16) * 128 + ks * 32 + b_colb));
                    uint32_t r[4];
                    ldmx4(r, tBh + off);
                    bh[jb * 2 + 0][0] = r[0]; bh[jb * 2 + 0][1] = r[2];
                    bh[jb * 2 + 1][0] = r[1]; bh[jb * 2 + 1][1] = r[3];
                    ldmx4(r, tBl + off);
                    bl[jb * 2 + 0][0] = r[0]; bl[jb * 2 + 0][1] = r[2];
                    bl[jb * 2 + 1][0] = r[1]; bl[jb * 2 + 1][1] = r[3];
                }
#pragma unroll
                for (int i = 0; i < 2; ++i)
#pragma unroll
                    for (int j = 0; j < 4; ++j)
                        mma_f16 (acc[i][j], ah[i], bh[j][0], bh[j][1]);  // hh
#pragma unroll
                for (int i = 0; i < 2; ++i)
#pragma unroll
                    for (int j = 0; j < 4; ++j)
                        mma_f16a(crs[i][j], ah[i], bl[j][0], bl[j][1]);  // hl
#pragma unroll
                for (int i = 0; i < 2; ++i)
#pragma unroll
                    for (int j = 0; j < 4; ++j)
                        mma_f16a(crs[i][j], al[i], bh[j][0], bh[j][1]);  // lh
            } else {
                uint32_t tAh = st;
                uint32_t tBh = st + TILE_BYTES;
                uint32_t ah[2][4];
#pragma unroll
                for (int i = 0; i < 2; ++i) {
                    uint32_t off = SWZ((uint32_t)((a_rowbase + i * 16) * 128 + ks * 32 + a_colb));
                    ldmx4(ah[i], tAh + off);
                }
                uint32_t bh[4][2];
#pragma unroll
                for (int jb = 0; jb < 2; ++jb) {
                    uint32_t off = SWZ((uint32_t)((b_rowbase + jb * 16) * 128 + ks * 32 + b_colb));
                    uint32_t r[4];
                    ldmx4(r, tBh + off);
                    bh[jb * 2 + 0][0] = r[0]; bh[jb * 2 + 0][1] = r[2];
                    bh[jb * 2 + 1][0] = r[1]; bh[jb * 2 + 1][1] = r[3];
                }
#pragma unroll
                for (int i = 0; i < 2; ++i)
#pragma unroll
                    for (int j = 0; j < 4; ++j)
                        mma_f16(acc[i][j], ah[i], bh[j][0], bh[j][1]);
            }
        }
        __syncthreads();
    }

    // Epilogue
    int g = lane >> 2, t = lane & 3;
#pragma unroll
    for (int i = 0; i < 2; ++i) {
        int r0 = m0 + warp_m * 32 + i * 16 + g;
        float rmax_lo = -3.0e38f, rmax_hi = -3.0e38f;  // OUTM==3 row maxima
#pragma unroll
        for (int j = 0; j < 4; ++j) {
            int col = n0 + warp_n * 32 + j * 8 + t * 2;
            float v0 = acc[i][j][0], v1 = acc[i][j][1];
            float v2 = acc[i][j][2], v3 = acc[i][j][3];
            if (ABM == 0) {
                __half2 c01 = *(__half2*)&crs[i][j][0];
                __half2 c23 = *(__half2*)&crs[i][j][1];
                v0 += __low2float(c01);  v1 += __high2float(c01);
                v2 += __low2float(c23);  v3 += __high2float(c23);
            }
            if (bias) {
                float b0 = __ldg(bias + col), b1 = __ldg(bias + col + 1);
                v0 += b0; v1 += b1; v2 += b0; v3 += b1;
            }
            if constexpr (OUTM == 0 || OUTM == 3) {
                *(float2*)(C + (size_t)r0 * N + col)       = make_float2(v0, v1);
                *(float2*)(C + (size_t)(r0 + 8) * N + col) = make_float2(v2, v3);
                if constexpr (OUTM == 3) {
                    rmax_lo = fmaxf(rmax_lo, fmaxf(v0, v1));
                    rmax_hi = fmaxf(rmax_hi, fmaxf(v2, v3));
                }
            } else {
                __half h0 = __float2half(v0), h1 = __float2half(v1);
                __half h2 = __float2half(v2), h3 = __float2half(v3);
                __half l0 = __float2half(v0 - __half2float(h0));
                __half l1 = __float2half(v1 - __half2float(h1));
                __half l2 = __float2half(v2 - __half2float(h2));
                __half l3 = __float2half(v3 - __half2float(h3));
                __half2 hh0; hh0.x = h0; hh0.y = h1;
                __half2 hh1; hh1.x = h2; hh1.y = h3;
                __half2 ll0; ll0.x = l0; ll0.y = l1;
                __half2 ll1; ll1.x = l2; ll1.y = l3;
                *(__half2*)(Chi + (size_t)r0 * N + col)       = hh0;
                *(__half2*)(Chi + (size_t)(r0 + 8) * N + col) = hh1;
                *(__half2*)(Clo + (size_t)r0 * N + col)       = ll0;
                *(__half2*)(Clo + (size_t)(r0 + 8) * N + col) = ll1;
            }
        }
        if constexpr (OUTM == 3) {
            // Reduce over the 4 lanes sharing each row (t = 0..3), then atomicMax.
            rmax_lo = fmaxf(rmax_lo, __shfl_xor_sync(0xFFFFFFFFu, rmax_lo, 1));
            rmax_lo = fmaxf(rmax_lo, __shfl_xor_sync(0xFFFFFFFFu, rmax_lo, 2));
            rmax_hi = fmaxf(rmax_hi, __shfl_xor_sync(0xFFFFFFFFu, rmax_hi, 1));
            rmax_hi = fmaxf(rmax_hi, __shfl_xor_sync(0xFFFFFFFFu, rmax_hi, 2));
            if (t == 0) {
                atomicMax(RM + r0,     enc_f32(rmax_lo));
                atomicMax(RM + r0 + 8, enc_f32(rmax_hi));
            }
        }
    }
}

// ---------------------------------------------------------------------------
// Fused fp32 -> (fp16 hi, fp16 lo) split for A, Wq, Wk + row-max init
// ---------------------------------------------------------------------------
__device__ __forceinline__ void split_one(const float* __restrict__ in,
                                          __half* __restrict__ hi,
                                          __half* __restrict__ lo,
                                          long long n, long long gtid, long long stride)
{
    for (long long i = gtid; i < n; i += stride) {
        float x = in[i];
        __half h = __float2half(x);
        hi[i] = h;
        lo[i] = __float2half(x - __half2float(h));
    }
}

__global__ void fused_split_kernel(
    const float* __restrict__ A,  __half* Ahi,  __half* Alo,  long long nA,
    const float* __restrict__ W1, __half* W1hi, __half* W1lo,
    const float* __restrict__ W2, __half* W2hi, __half* W2lo, long long nW,
    uint32_t* __restrict__ RM)
{
    long long gtid = (long long)blockIdx.x * blockDim.x + threadIdx.x;
    long long stride = (long long)gridDim.x * blockDim.x;
    if (gtid < 8192) RM[gtid] = ENC_NEG_INF;  // init row-max accumulators
    split_one(A,  Ahi,  Alo,  nA, gtid, stride);
    split_one(W1, W1hi, W1lo, nW, gtid, stride);
    split_one(W2, W2hi, W2lo, nW, gtid, stride);
}

// ---------------------------------------------------------------------------
// X: one read -> (fp16 hi, fp16 lo) linear + fp16 transposed [C,R]
// ---------------------------------------------------------------------------
__global__ void xsplit_kernel(const float* __restrict__ X,
                              __half* __restrict__ hi,
                              __half* __restrict__ lo,
                              __half* __restrict__ xt, int R, int C)
{
    __shared__ float tbuf[32][33];
    int c0 = blockIdx.x * 32, r0 = blockIdx.y * 32;
    int tx = threadIdx.x, ty = threadIdx.y;
#pragma unroll
    for (int j = 0; j < 4; ++j) {
        int r = r0 + ty + 8 * j;
        float v = X[(long long)r * C + c0 + tx];
        tbuf[ty + 8 * j][tx] = v;
        __half h = __float2half(v);
        hi[(long long)r * C + c0 + tx] = h;
        lo[(long long)r * C + c0 + tx] = __float2half(v - __half2float(h));
    }
    __syncthreads();
#pragma unroll
    for (int j = 0; j < 4; ++j) {
        float v = tbuf[tx][ty + 8 * j];
        xt[(long long)(c0 + ty + 8 * j) * R + r0 + tx] = __float2half(v);
    }
}

// ---------------------------------------------------------------------------
// Row softmax with precomputed row max (single gmem pass over S)
// ---------------------------------------------------------------------------
__global__ void __launch_bounds__(256) softmax_kernel(
    const float* __restrict__ S, const uint32_t* __restrict__ RM,
    __half* __restrict__ P, int N)
{
    __shared__ float buf[8192];
    __shared__ float red[8];
    int row = blockIdx.x, tid = threadIdx.x;
    const float* s = S + (long long)row * N;
    float mx = dec_f32(__ldg(RM + row));

    float sum = 0.0f;
    for (int i = tid; i < N; i += 256) {
        float e = __expf(s[i] - mx);
        buf[i] = e;
        sum += e;
    }
#pragma unroll
    for (int o = 16; o; o >>= 1) sum += __shfl_xor_sync(0xFFFFFFFFu, sum, o);
    if ((tid & 31) == 0) red[tid >> 5] = sum;
    __syncthreads();
    sum = 0.0f;
#pragma unroll
    for (int w = 0; w < 8; ++w) sum += red[w];
    float inv = 1.0f / sum;

    for (int i = tid; i < N; i += 256)
        P[(long long)row * N + i] = __float2half(buf[i] * inv);
}

// ---------------------------------------------------------------------------
// Scratch
// ---------------------------------------------------------------------------
static constexpr size_t SZ_AX = (size_t)8192 * 1024;
static constexpr size_t SZ_W  = (size_t)512 * 1024;
static constexpr size_t SZ_QK = (size_t)8192 * 512;
static constexpr size_t SZ_S  = (size_t)8192 * 8192;

static constexpr size_t OFF_AHI  = 0;
static constexpr size_t OFF_ALO  = OFF_AHI  + SZ_AX * 2;
static constexpr size_t OFF_XHI  = OFF_ALO  + SZ_AX * 2;
static constexpr size_t OFF_XLO  = OFF_XHI  + SZ_AX * 2;
static constexpr size_t OFF_WQHI = OFF_XLO  + SZ_AX * 2;
static constexpr size_t OFF_WQLO = OFF_WQHI + SZ_W * 2;
static constexpr size_t OFF_WKHI = OFF_WQLO + SZ_W * 2;
static constexpr size_t OFF_WKLO = OFF_WKHI + SZ_W * 2;
static constexpr size_t OFF_QHI  = OFF_WKLO + SZ_W * 2;
static constexpr size_t OFF_QLO  = OFF_QHI  + SZ_QK * 2;
static constexpr size_t OFF_KHI  = OFF_QLO  + SZ_QK * 2;
static constexpr size_t OFF_KLO  = OFF_KHI  + SZ_QK * 2;
static constexpr size_t OFF_S    = OFF_KLO  + SZ_QK * 2;
static constexpr size_t OFF_PHI  = OFF_S    + SZ_S * 4;
static constexpr size_t OFF_XTHI = OFF_PHI  + SZ_S * 2;
static constexpr size_t OFF_RM   = OFF_XTHI + SZ_AX * 2;
static constexpr size_t SCRATCH_TOTAL = OFF_RM + 8192 * 4;

__device__ __align__(256) unsigned char g_scratch[SCRATCH_TOTAL];

// ---------------------------------------------------------------------------
// kernel_launch
// ---------------------------------------------------------------------------
extern "C" void kernel_launch(void* const* d_in, const int* in_sizes, int n_in,
                              void* d_out, int out_size)
{
    const float* A  = (const float*)d_in[0];
    const float* X  = (const float*)d_in[1];
    const float* Wq = (const float*)d_in[2];
    const float* bq = (const float*)d_in[3];
    const float* Wk = (const float*)d_in[4];
    const float* bk = (const float*)d_in[5];
    float* out = (float*)d_out;

    unsigned char* s = nullptr;
    cudaGetSymbolAddress((void**)&s, g_scratch);
    auto H   = [&](size_t off) { return (__half*)(s + off); };
    auto U16 = [&](size_t off) { return (const uint16_t*)(s + off); };
    auto F   = [&](size_t off) { return (float*)(s + off); };
    uint32_t* RM = (uint32_t*)(s + OFF_RM);

    // One-time stream/event setup (first call is not graph-captured).
    static cudaStream_t s1 = nullptr;
    static cudaEvent_t evRoot = nullptr, evSplit = nullptr, evQ = nullptr;
    if (!s1) {
        cudaStreamCreateWithFlags(&s1, cudaStreamNonBlocking);
        cudaEventCreateWithFlags(&evRoot,  cudaEventDisableTiming);
        cudaEventCreateWithFlags(&evSplit, cudaEventDisableTiming);
        cudaEventCreateWithFlags(&evQ,     cudaEventDisableTiming);
    }

    cudaFuncSetAttribute(gemm_kernel<0, 3>,
                         cudaFuncAttributeMaxDynamicSharedMemorySize, Cfg<0>::SMEM);
    cudaFuncSetAttribute(gemm_kernel<0, 1>,
                         cudaFuncAttributeMaxDynamicSharedMemorySize, Cfg<0>::SMEM);
    cudaFuncSetAttribute(gemm_kernel<2, 0>,
                         cudaFuncAttributeMaxDynamicSharedMemorySize, Cfg<2>::SMEM);

    // Fork side stream from main stream.
    cudaEventRecord(evRoot, 0);
    cudaStreamWaitEvent(s1, evRoot, 0);

    // s1: split A/Wq/Wk (+RM init), then Q GEMM.
    fused_split_kernel<<<2048, 256, 0, s1>>>(
        A,  H(OFF_AHI),  H(OFF_ALO),  (long long)SZ_AX,
        Wq, H(OFF_WQHI), H(OFF_WQLO),
        Wk, H(OFF_WKHI), H(OFF_WKLO), (long long)SZ_W, RM);
    cudaEventRecord(evSplit, s1);

    dim3 gq(512 / 128, 8192 / 128);
    gemm_kernel<0, 1><<<gq, 512, Cfg<0>::SMEM, s1>>>(
        U16(OFF_AHI), U16(OFF_ALO), U16(OFF_WQHI), U16(OFF_WQLO),
        nullptr, H(OFF_QHI), H(OFF_QLO), nullptr, 8192, 512, 1024, bq);
    cudaEventRecord(evQ, s1);

    // main stream: X split (concurrent with fused_split), then K GEMM
    // (needs Wk halves from s1 -> wait evSplit; runs concurrent with Q GEMM).
    xsplit_kernel<<<dim3(1024 / 32, 8192 / 32), dim3(32, 8)>>>(
        X, H(OFF_XHI), H(OFF_XLO), H(OFF_XTHI), 8192, 1024);
    cudaStreamWaitEvent(0, evSplit, 0);
    gemm_kernel<0, 1><<<gq, 512, Cfg<0>::SMEM>>>(
        U16(OFF_XHI), U16(OFF_XLO), U16(OFF_WKHI), U16(OFF_WKLO),
        nullptr, H(OFF_KHI), H(OFF_KLO), nullptr, 8192, 512, 1024, bk);

    // Join: S needs Q (s1) and K (main).
    cudaStreamWaitEvent(0, evQ, 0);

    // S = Q @ K^T with row-max epilogue (M=N=8192, K=512)
    dim3 gs(8192 / 128, 8192 / 128);
    gemm_kernel<0, 3><<<gs, 512, Cfg<0>::SMEM>>>(
        U16(OFF_QHI), U16(OFF_QLO), U16(OFF_KHI), U16(OFF_KLO),
        F(OFF_S), nullptr, nullptr, RM, 8192, 8192, 512, nullptr);

    // P = softmax(S) -> fp16 (single pass; max precomputed)
    softmax_kernel<<<8192, 256>>>(F(OFF_S), RM, (__half*)(s + OFF_PHI), 8192);

    // O = P @ X (M=8192, N=1024, K=8192)
    dim3 go(1024 / 128, 8192 / 128);
    gemm_kernel<2, 0><<<go, 512, Cfg<2>::SMEM>>>(
        U16(OFF_PHI), nullptr, U16(OFF_XTHI), nullptr,
        out, nullptr, nullptr, nullptr, 8192, 1024, 8192, nullptr);
}

// round 13
// speedup vs baseline: 1.0116x; 1.0054x over previous
#include <cuda_runtime.h>
#include <cuda_bf16.h>
#include <cuda_fp16.h>
#include <cstdint>

// ============================================================================
// AWAttention on B200, baseline sm_100 mma.sync path.
//   Q = A@Wq^T + bq ; K = X@Wk^T + bk ; S = Q@K^T ; P = softmax(S) ; O = P@X
// Precision scheme (fp16 hi+lo split):
//   ABM=0 (Q/K/S): hh -> fp32-acc MMA ; hl+lh -> fp16-acc MMA.
//   ABM=2 (O):     E_fp16 @ Xhi_fp16, fp32 acc, scaled by 1/rowsum in epilogue.
// R13: softmax is a single pass writing UNNORMALIZED E=exp(s-rowmax)<=1 (fp16
//      safe) + rowsum RS; O epilogue multiplies by 1/RS[row].
// OUT modes: 0 = fp32 C ; 1 = split-fp16 epilogue (Q/K) ;
//            3 = fp32 C + row-max atomics (S) ; 4 = fp32 C scaled by 1/RS (O).
// ============================================================================

#define SWZ(x) ((x) ^ (((x) >> 3) & 0x70))

__device__ __forceinline__ uint32_t smem_u32(const void* p) {
    uint32_t a;
    asm("{ .reg .u64 t; cvta.to.shared.u64 t, %1; cvt.u32.u64 %0, t; }" : "=r"(a) : "l"(p));
    return a;
}

// Monotone encode: enc(x) preserves float order in uint order.
__device__ __forceinline__ uint32_t enc_f32(float x) {
    uint32_t b = __float_as_uint(x);
    return (b & 0x80000000u) ? ~b : (b | 0x80000000u);
}
__device__ __forceinline__ float dec_f32(uint32_t u) {
    uint32_t b = (u & 0x80000000u) ? (u ^ 0x80000000u) : ~u;
    return __uint_as_float(b);
}
static constexpr uint32_t ENC_NEG_INF = 0x007FFFFFu;

#define CP_ASYNC16(sm, gm) \
    asm volatile("cp.async.cg.shared.global [%0], [%1], 16;" :: "r"(sm), "l"(gm))
#define CP_COMMIT() asm volatile("cp.async.commit_group;" ::: "memory")

__device__ __forceinline__ void ldmx4(uint32_t r[4], uint32_t addr) {
    asm volatile("ldmatrix.sync.aligned.m8n8.x4.shared.b16 {%0,%1,%2,%3}, [%4];"
                 : "=r"(r[0]), "=r"(r[1]), "=r"(r[2]), "=r"(r[3]) : "r"(addr));
}

__device__ __forceinline__ void mma_f16(float c[4], const uint32_t a[4],
                                        uint32_t b0, uint32_t b1) {
    asm volatile(
        "mma.sync.aligned.m16n8k16.row.col.f32.f16.f16.f32 "
        "{%0,%1,%2,%3}, {%4,%5,%6,%7}, {%8,%9}, {%0,%1,%2,%3};"
        : "+f"(c[0]), "+f"(c[1]), "+f"(c[2]), "+f"(c[3])
        : "r"(a[0]), "r"(a[1]), "r"(a[2]), "r"(a[3]), "r"(b0), "r"(b1));
}

__device__ __forceinline__ void mma_f16a(uint32_t c[2], const uint32_t a[4],
                                         uint32_t b0, uint32_t b1) {
    asm volatile(
        "mma.sync.aligned.m16n8k16.row.col.f16.f16.f16.f16 "
        "{%0,%1}, {%2,%3,%4,%5}, {%6,%7}, {%0,%1};"
        : "+r"(c[0]), "+r"(c[1])
        : "r"(a[0]), "r"(a[1]), "r"(a[2]), "r"(a[3]), "r"(b0), "r"(b1));
}

static constexpr int TILE_BYTES = 128 * 128;

template <int ABM> struct Cfg {
    static constexpr int NT  = (ABM == 0) ? 4 : 2;
    static constexpr int STG = (ABM == 0) ? 3 : 6;
    static constexpr int STAGE_B = NT * TILE_BYTES;
    static constexpr int SMEM = STG * STAGE_B;
};

template <int ABM>
__device__ __forceinline__ void load_chunk(
    uint32_t stage, const uint16_t* __restrict__ Ah, const uint16_t* __restrict__ Al,
    const uint16_t* __restrict__ Bh, const uint16_t* __restrict__ Bl,
    int m0, int n0, int kc, int K, int tid)
{
#pragma unroll
    for (int i = 0; i < 2; ++i) {
        int ch  = tid + i * 512;
        int row = ch >> 3;
        int c16 = ch & 7;
        uint32_t soff = SWZ((uint32_t)(row * 128 + c16 * 16));
        size_t ga = ((size_t)(m0 + row) * K + (size_t)kc * 64) * 2 + (size_t)c16 * 16;
        size_t gb = ((size_t)(n0 + row) * K + (size_t)kc * 64) * 2 + (size_t)c16 * 16;
        if (ABM == 0) {
            CP_ASYNC16(stage + 0 * TILE_BYTES + soff, (const char*)Ah + ga);
            CP_ASYNC16(stage + 1 * TILE_BYTES + soff, (const char*)Al + ga);
            CP_ASYNC16(stage + 2 * TILE_BYTES + soff, (const char*)Bh + gb);
            CP_ASYNC16(stage + 3 * TILE_BYTES + soff, (const char*)Bl + gb);
        } else {
            CP_ASYNC16(stage + 0 * TILE_BYTES + soff, (const char*)Ah + ga);
            CP_ASYNC16(stage + 1 * TILE_BYTES + soff, (const char*)Bh + gb);
        }
    }
}

template <int ABM, int OUTM>
__global__ void __launch_bounds__(512, 1) gemm_kernel(
    const uint16_t* __restrict__ Ah, const uint16_t* __restrict__ Al,
    const uint16_t* __restrict__ Bh, const uint16_t* __restrict__ Bl,
    float* __restrict__ C, __half* __restrict__ Chi,
    __half* __restrict__ Clo, uint32_t* __restrict__ RM,
    int M, int N, int K, const float* __restrict__ bias)
{
    constexpr int STG = Cfg<ABM>::STG;
    constexpr int STAGE_B = Cfg<ABM>::STAGE_B;

    extern __shared__ __align__(1024) unsigned char smem[];
    uint32_t sbase = smem_u32(smem);
    int tid = threadIdx.x, wid = tid >> 5, lane = tid & 31;
    int warp_m = wid & 3;
    int warp_n = wid >> 2;
    int m0 = blockIdx.y * 128, n0 = blockIdx.x * 128;

    float acc[2][4][4];
    uint32_t crs[2][4][2];
#pragma unroll
    for (int i = 0; i < 2; ++i)
#pragma unroll
        for (int j = 0; j < 4; ++j) {
#pragma unroll
            for (int e = 0; e < 4; ++e) acc[i][j][e] = 0.0f;
            crs[i][j][0] = 0u; crs[i][j][1] = 0u;
        }

    const int nch = K >> 6;

#pragma unroll
    for (int s = 0; s < STG - 1; ++s) {
        if (s < nch)
            load_chunk<ABM>(sbase + s * STAGE_B, Ah, Al, Bh, Bl, m0, n0, s, K, tid);
        CP_COMMIT();
    }

    const int a_rowbase = warp_m * 32 + (lane & 15);
    const int a_colb    = (lane >> 4) * 16;
    const int b_rowbase = warp_n * 32 + (lane & 7) + ((lane >> 3) & 1) * 8;
    const int b_colb    = (lane >> 4) * 16;

    for (int c = 0; c < nch; ++c) {
        if constexpr (STG == 3)      asm volatile("cp.async.wait_group 1;" ::: "memory");
        else                         asm volatile("cp.async.wait_group 4;" ::: "memory");
        __syncthreads();

        int nextc = c + STG - 1;
        if (nextc < nch)
            load_chunk<ABM>(sbase + (uint32_t)(nextc % STG) * STAGE_B,
                            Ah, Al, Bh, Bl, m0, n0, nextc, K, tid);
        CP_COMMIT();

        uint32_t st = sbase + (uint32_t)(c % STG) * STAGE_B;

#pragma unroll
        for (int ks = 0; ks < 4; ++ks) {
            if (ABM == 0) {
                uint32_t tAh = st, tAl = st + TILE_BYTES;
                uint32_t tBh = st + 2 * TILE_BYTES, tBl = st + 3 * TILE_BYTES;
                uint32_t ah[2][4], al[2][4];
#pragma unroll
                for (int i = 0; i < 2; ++i) {
                    uint32_t off = SWZ((uint32_t)((a_rowbase + i * 16) * 128 + ks * 32 + a_colb));
                    ldmx4(ah[i], tAh + off);
                    ldmx4(al[i], tAl + off);
                }
                uint32_t bh[4][2], bl[4][2];
#pragma unroll
                for (int jb = 0; jb < 2; ++jb) {
                    uint32_t off = SWZ((uint32_t)((b_rowbase + jb * 16) * 128 + ks * 32 + b_colb));
                    uint32_t r[4];
                    ldmx4(r, tBh + off);
                    bh[jb * 2 + 0][0] = r[0]; bh[jb * 2 + 0][1] = r[2];
                    bh[jb * 2 + 1][0] = r[1]; bh[jb * 2 + 1][1] = r[3];
                    ldmx4(r, tBl + off);
                    bl[jb * 2 + 0][0] = r[0]; bl[jb * 2 + 0][1] = r[2];
                    bl[jb * 2 + 1][0] = r[1]; bl[jb * 2 + 1][1] = r[3];
                }
#pragma unroll
                for (int i = 0; i < 2; ++i)
#pragma unroll
                    for (int j = 0; j < 4; ++j)
                        mma_f16 (acc[i][j], ah[i], bh[j][0], bh[j][1]);  // hh
#pragma unroll
                for (int i = 0; i < 2; ++i)
#pragma unroll
                    for (int j = 0; j < 4; ++j)
                        mma_f16a(crs[i][j], ah[i], bl[j][0], bl[j][1]);  // hl
#pragma unroll
                for (int i = 0; i < 2; ++i)
#pragma unroll
                    for (int j = 0; j < 4; ++j)
                        mma_f16a(crs[i][j], al[i], bh[j][0], bh[j][1]);  // lh
            } else {
                uint32_t tAh = st;
                uint32_t tBh = st + TILE_BYTES;
                uint32_t ah[2][4];
#pragma unroll
                for (int i = 0; i < 2; ++i) {
                    uint32_t off = SWZ((uint32_t)((a_rowbase + i * 16) * 128 + ks * 32 + a_colb));
                    ldmx4(ah[i], tAh + off);
                }
                uint32_t bh[4][2];
#pragma unroll
                for (int jb = 0; jb < 2; ++jb) {
                    uint32_t off = SWZ((uint32_t)((b_rowbase + jb * 16) * 128 + ks * 32 + b_colb));
                    uint32_t r[4];
                    ldmx4(r, tBh + off);
                    bh[jb * 2 + 0][0] = r[0]; bh[jb * 2 + 0][1] = r[2];
                    bh[jb * 2 + 1][0] = r[1]; bh[jb * 2 + 1][1] = r[3];
                }
#pragma unroll
                for (int i = 0; i < 2; ++i)
#pragma unroll
                    for (int j = 0; j < 4; ++j)
                        mma_f16(acc[i][j], ah[i], bh[j][0], bh[j][1]);
            }
        }
        __syncthreads();
    }

    // Epilogue
    int g = lane >> 2, t = lane & 3;
    const float* RSf = (const float*)RM;  // OUTM==4: row-sum array
#pragma unroll
    for (int i = 0; i < 2; ++i) {
        int r0 = m0 + warp_m * 32 + i * 16 + g;
        float rmax_lo = -3.0e38f, rmax_hi = -3.0e38f;
        float inv_lo = 1.0f, inv_hi = 1.0f;
        if constexpr (OUTM == 4) {
            inv_lo = 1.0f / __ldg(RSf + r0);
            inv_hi = 1.0f / __ldg(RSf + r0 + 8);
        }
#pragma unroll
        for (int j = 0; j < 4; ++j) {
            int col = n0 + warp_n * 32 + j * 8 + t * 2;
            float v0 = acc[i][j][0], v1 = acc[i][j][1];
            float v2 = acc[i][j][2], v3 = acc[i][j][3];
            if (ABM == 0) {
                __half2 c01 = *(__half2*)&crs[i][j][0];
                __half2 c23 = *(__half2*)&crs[i][j][1];
                v0 += __low2float(c01);  v1 += __high2float(c01);
                v2 += __low2float(c23);  v3 += __high2float(c23);
            }
            if (bias) {
                float b0 = __ldg(bias + col), b1 = __ldg(bias + col + 1);
                v0 += b0; v1 += b1; v2 += b0; v3 += b1;
            }
            if constexpr (OUTM == 4) {
                v0 *= inv_lo; v1 *= inv_lo; v2 *= inv_hi; v3 *= inv_hi;
            }
            if constexpr (OUTM == 0 || OUTM == 3 || OUTM == 4) {
                *(float2*)(C + (size_t)r0 * N + col)       = make_float2(v0, v1);
                *(float2*)(C + (size_t)(r0 + 8) * N + col) = make_float2(v2, v3);
                if constexpr (OUTM == 3) {
                    rmax_lo = fmaxf(rmax_lo, fmaxf(v0, v1));
                    rmax_hi = fmaxf(rmax_hi, fmaxf(v2, v3));
                }
            } else {
                __half h0 = __float2half(v0), h1 = __float2half(v1);
                __half h2 = __float2half(v2), h3 = __float2half(v3);
                __half l0 = __float2half(v0 - __half2float(h0));
                __half l1 = __float2half(v1 - __half2float(h1));
                __half l2 = __float2half(v2 - __half2float(h2));
                __half l3 = __float2half(v3 - __half2float(h3));
                __half2 hh0; hh0.x = h0; hh0.y = h1;
                __half2 hh1; hh1.x = h2; hh1.y = h3;
                __half2 ll0; ll0.x = l0; ll0.y = l1;
                __half2 ll1; ll1.x = l2; ll1.y = l3;
                *(__half2*)(Chi + (size_t)r0 * N + col)       = hh0;
                *(__half2*)(Chi + (size_t)(r0 + 8) * N + col) = hh1;
                *(__half2*)(Clo + (size_t)r0 * N + col)       = ll0;
                *(__half2*)(Clo + (size_t)(r0 + 8) * N + col) = ll1;
            }
        }
        if constexpr (OUTM == 3) {
            rmax_lo = fmaxf(rmax_lo, __shfl_xor_sync(0xFFFFFFFFu, rmax_lo, 1));
            rmax_lo = fmaxf(rmax_lo, __shfl_xor_sync(0xFFFFFFFFu, rmax_lo, 2));
            rmax_hi = fmaxf(rmax_hi, __shfl_xor_sync(0xFFFFFFFFu, rmax_hi, 1));
            rmax_hi = fmaxf(rmax_hi, __shfl_xor_sync(0xFFFFFFFFu, rmax_hi, 2));
            if (t == 0) {
                atomicMax(RM + r0,     enc_f32(rmax_lo));
                atomicMax(RM + r0 + 8, enc_f32(rmax_hi));
            }
        }
    }
}

// ---------------------------------------------------------------------------
// Fused fp32 -> (fp16 hi, fp16 lo) split for A, Wq, Wk + row-max init
// ---------------------------------------------------------------------------
__device__ __forceinline__ void split_one(const float* __restrict__ in,
                                          __half* __restrict__ hi,
                                          __half* __restrict__ lo,
                                          long long n, long long gtid, long long stride)
{
    for (long long i = gtid; i < n; i += stride) {
        float x = in[i];
        __half h = __float2half(x);
        hi[i] = h;
        lo[i] = __float2half(x - __half2float(h));
    }
}

__global__ void fused_split_kernel(
    const float* __restrict__ A,  __half* Ahi,  __half* Alo,  long long nA,
    const float* __restrict__ W1, __half* W1hi, __half* W1lo,
    const float* __restrict__ W2, __half* W2hi, __half* W2lo, long long nW,
    uint32_t* __restrict__ RM)
{
    long long gtid = (long long)blockIdx.x * blockDim.x + threadIdx.x;
    long long stride = (long long)gridDim.x * blockDim.x;
    if (gtid < 8192) RM[gtid] = ENC_NEG_INF;
    split_one(A,  Ahi,  Alo,  nA, gtid, stride);
    split_one(W1, W1hi, W1lo, nW, gtid, stride);
    split_one(W2, W2hi, W2lo, nW, gtid, stride);
}

// ---------------------------------------------------------------------------
// X: one read -> (fp16 hi, fp16 lo) linear + fp16 transposed [C,R]
// ---------------------------------------------------------------------------
__global__ void xsplit_kernel(const float* __restrict__ X,
                              __half* __restrict__ hi,
                              __half* __restrict__ lo,
                              __half* __restrict__ xt, int R, int C)
{
    __shared__ float tbuf[32][33];
    int c0 = blockIdx.x * 32, r0 = blockIdx.y * 32;
    int tx = threadIdx.x, ty = threadIdx.y;
#pragma unroll
    for (int j = 0; j < 4; ++j) {
        int r = r0 + ty + 8 * j;
        float v = X[(long long)r * C + c0 + tx];
        tbuf[ty + 8 * j][tx] = v;
        __half h = __float2half(v);
        hi[(long long)r * C + c0 + tx] = h;
        lo[(long long)r * C + c0 + tx] = __float2half(v - __half2float(h));
    }
    __syncthreads();
#pragma unroll
    for (int j = 0; j < 4; ++j) {
        float v = tbuf[tx][ty + 8 * j];
        xt[(long long)(c0 + ty + 8 * j) * R + r0 + tx] = __float2half(v);
    }
}

// ---------------------------------------------------------------------------
// Single-pass: E = exp(S - rowmax) -> fp16 (unnormalized, <=1), rowsum -> RS
// ---------------------------------------------------------------------------
__global__ void __launch_bounds__(256) softmax_e_kernel(
    const float4* __restrict__ S4, const uint32_t* __restrict__ RM,
    uint2* __restrict__ E4, float* __restrict__ RS)
{
    __shared__ float red[8];
    int row = blockIdx.x, tid = threadIdx.x;
    float mx = dec_f32(__ldg(RM + row));
    const float4* s = S4 + (size_t)row * 2048;
    uint2* e = E4 + (size_t)row * 2048;

    float sum = 0.0f;
    for (int i = tid; i < 2048; i += 256) {
        float4 v = s[i];
        float e0 = __expf(v.x - mx), e1 = __expf(v.y - mx);
        float e2 = __expf(v.z - mx), e3 = __expf(v.w - mx);
        __half2 h0 = __floats2half2_rn(e0, e1);
        __half2 h1 = __floats2half2_rn(e2, e3);
        uint2 pk;
        pk.x = *(uint32_t*)&h0;
        pk.y = *(uint32_t*)&h1;
        e[i] = pk;
        sum += (e0 + e1) + (e2 + e3);
    }
#pragma unroll
    for (int o = 16; o; o >>= 1) sum += __shfl_xor_sync(0xFFFFFFFFu, sum, o);
    if ((tid & 31) == 0) red[tid >> 5] = sum;
    __syncthreads();
    if (tid == 0) {
        float t = 0.0f;
#pragma unroll
        for (int w = 0; w < 8; ++w) t += red[w];
        RS[row] = t;
    }
}

// ---------------------------------------------------------------------------
// Scratch
// ---------------------------------------------------------------------------
static constexpr size_t SZ_AX = (size_t)8192 * 1024;
static constexpr size_t SZ_W  = (size_t)512 * 1024;
static constexpr size_t SZ_QK = (size_t)8192 * 512;
static constexpr size_t SZ_S  = (size_t)8192 * 8192;

static constexpr size_t OFF_AHI  = 0;
static constexpr size_t OFF_ALO  = OFF_AHI  + SZ_AX * 2;
static constexpr size_t OFF_XHI  = OFF_ALO  + SZ_AX * 2;
static constexpr size_t OFF_XLO  = OFF_XHI  + SZ_AX * 2;
static constexpr size_t OFF_WQHI = OFF_XLO  + SZ_AX * 2;
static constexpr size_t OFF_WQLO = OFF_WQHI + SZ_W * 2;
static constexpr size_t OFF_WKHI = OFF_WQLO + SZ_W * 2;
static constexpr size_t OFF_WKLO = OFF_WKHI + SZ_W * 2;
static constexpr size_t OFF_QHI  = OFF_WKLO + SZ_W * 2;
static constexpr size_t OFF_QLO  = OFF_QHI  + SZ_QK * 2;
static constexpr size_t OFF_KHI  = OFF_QLO  + SZ_QK * 2;
static constexpr size_t OFF_KLO  = OFF_KHI  + SZ_QK * 2;
static constexpr size_t OFF_S    = OFF_KLO  + SZ_QK * 2;
static constexpr size_t OFF_PHI  = OFF_S    + SZ_S * 4;
static constexpr size_t OFF_XTHI = OFF_PHI  + SZ_S * 2;
static constexpr size_t OFF_RM   = OFF_XTHI + SZ_AX * 2;
static constexpr size_t OFF_RS   = OFF_RM   + 8192 * 4;
static constexpr size_t SCRATCH_TOTAL = OFF_RS + 8192 * 4;

__device__ __align__(256) unsigned char g_scratch[SCRATCH_TOTAL];

// ---------------------------------------------------------------------------
// kernel_launch
// ---------------------------------------------------------------------------
extern "C" void kernel_launch(void* const* d_in, const int* in_sizes, int n_in,
                              void* d_out, int out_size)
{
    const float* A  = (const float*)d_in[0];
    const float* X  = (const float*)d_in[1];
    const float* Wq = (const float*)d_in[2];
    const float* bq = (const float*)d_in[3];
    const float* Wk = (const float*)d_in[4];
    const float* bk = (const float*)d_in[5];
    float* out = (float*)d_out;

    unsigned char* s = nullptr;
    cudaGetSymbolAddress((void**)&s, g_scratch);
    auto H   = [&](size_t off) { return (__half*)(s + off); };
    auto U16 = [&](size_t off) { return (const uint16_t*)(s + off); };
    auto F   = [&](size_t off) { return (float*)(s + off); };
    uint32_t* RM = (uint32_t*)(s + OFF_RM);
    float*    RS = (float*)(s + OFF_RS);

    static cudaStream_t s1 = nullptr;
    static cudaEvent_t evRoot = nullptr, evSplit = nullptr, evQ = nullptr;
    if (!s1) {
        cudaStreamCreateWithFlags(&s1, cudaStreamNonBlocking);
        cudaEventCreateWithFlags(&evRoot,  cudaEventDisableTiming);
        cudaEventCreateWithFlags(&evSplit, cudaEventDisableTiming);
        cudaEventCreateWithFlags(&evQ,     cudaEventDisableTiming);
    }

    cudaFuncSetAttribute(gemm_kernel<0, 3>,
                         cudaFuncAttributeMaxDynamicSharedMemorySize, Cfg<0>::SMEM);
    cudaFuncSetAttribute(gemm_kernel<0, 1>,
                         cudaFuncAttributeMaxDynamicSharedMemorySize, Cfg<0>::SMEM);
    cudaFuncSetAttribute(gemm_kernel<2, 4>,
                         cudaFuncAttributeMaxDynamicSharedMemorySize, Cfg<2>::SMEM);

    cudaEventRecord(evRoot, 0);
    cudaStreamWaitEvent(s1, evRoot, 0);

    // s1: split A/Wq/Wk (+RM init), then Q GEMM.
    fused_split_kernel<<<2048, 256, 0, s1>>>(
        A,  H(OFF_AHI),  H(OFF_ALO),  (long long)SZ_AX,
        Wq, H(OFF_WQHI), H(OFF_WQLO),
        Wk, H(OFF_WKHI), H(OFF_WKLO), (long long)SZ_W, RM);
    cudaEventRecord(evSplit, s1);

    dim3 gq(512 / 128, 8192 / 128);
    gemm_kernel<0, 1><<<gq, 512, Cfg<0>::SMEM, s1>>>(
        U16(OFF_AHI), U16(OFF_ALO), U16(OFF_WQHI), U16(OFF_WQLO),
        nullptr, H(OFF_QHI), H(OFF_QLO), nullptr, 8192, 512, 1024, bq);
    cudaEventRecord(evQ, s1);

    // main: X split, then K GEMM (waits for Wk halves; concurrent with Q GEMM)
    xsplit_kernel<<<dim3(1024 / 32, 8192 / 32), dim3(32, 8)>>>(
        X, H(OFF_XHI), H(OFF_XLO), H(OFF_XTHI), 8192, 1024);
    cudaStreamWaitEvent(0, evSplit, 0);
    gemm_kernel<0, 1><<<gq, 512, Cfg<0>::SMEM>>>(
        U16(OFF_XHI), U16(OFF_XLO), U16(OFF_WKHI), U16(OFF_WKLO),
        nullptr, H(OFF_KHI), H(OFF_KLO), nullptr, 8192, 512, 1024, bk);

    cudaStreamWaitEvent(0, evQ, 0);

    // S = Q @ K^T with row-max epilogue (M=N=8192, K=512)
    dim3 gs(8192 / 128, 8192 / 128);
    gemm_kernel<0, 3><<<gs, 512, Cfg<0>::SMEM>>>(
        U16(OFF_QHI), U16(OFF_QLO), U16(OFF_KHI), U16(OFF_KLO),
        F(OFF_S), nullptr, nullptr, RM, 8192, 8192, 512, nullptr);

    // E = exp(S - rowmax) -> fp16, rowsum -> RS (single pass)
    softmax_e_kernel<<<8192, 256>>>(
        (const float4*)F(OFF_S), RM, (uint2*)(s + OFF_PHI), RS);

    // O = (E @ X) / RS   (M=8192, N=1024, K=8192)
    dim3 go(1024 / 128, 8192 / 128);
    gemm_kernel<2, 4><<<go, 512, Cfg<2>::SMEM>>>(
        U16(OFF_PHI), nullptr, U16(OFF_XTHI), nullptr,
        out, nullptr, nullptr, (uint32_t*)RS, 8192, 1024, 8192, nullptr);
}